// round 1
// baseline (speedup 1.0000x reference)
#include <cuda_runtime.h>
#include <cstdint>

// Problem constants
#define T_STEPS 1024
#define BATCH   16
#define NHEADS  12
#define HD      64
#define NG      4
#define NCELLS  (BATCH * NHEADS)          // 192
#define CELLSTR (HD * NG)                 // 256 floats per (t,b,n)
#define TSTRIDE (NCELLS * CELLSTR)        // 49152 floats per timestep of Wx
#define OROW    ((size_t)NCELLS * HD)     // 12288 floats per timestep of out

typedef unsigned long long ull;

__device__ __forceinline__ ull pk2(float lo, float hi) {
    ull r;
    asm("mov.b64 %0, {%1, %2};" : "=l"(r) : "r"(__float_as_uint(lo)), "r"(__float_as_uint(hi)));
    return r;
}
__device__ __forceinline__ void upk2(ull v, float& lo, float& hi) {
    unsigned a, b2;
    asm("mov.b64 {%0, %1}, %2;" : "=r"(a), "=r"(b2) : "l"(v));
    lo = __uint_as_float(a);
    hi = __uint_as_float(b2);
}
// Packed dual FMA: acc.{lo,hi} += a.{lo,hi} * b.{lo,hi}  (FFMA2 in SASS)
__device__ __forceinline__ void ffma2(ull& acc, ull a, ull b) {
    asm("fma.rn.f32x2 %0, %1, %2, %0;" : "+l"(acc) : "l"(a), "l"(b));
}

// Fast, accurate-enough activations (MUFU.EX2 + MUFU.RCP based; rel err ~1e-7)
__device__ __forceinline__ float fsigmoid(float x) {
    return __fdividef(1.0f, 1.0f + __expf(-x));
}
__device__ __forceinline__ float ftanh_f(float x) {
    // tanh(x) = 1 - 2/(exp(2x)+1); saturates correctly for |x| large
    float e = __expf(2.0f * x);
    return 1.0f - __fdividef(2.0f, e + 1.0f);
}

__global__ void __launch_bounds__(256, 2)
flashrnn_lstm_kernel(const float* __restrict__ Wx,
                     const float* __restrict__ S0,
                     const float* __restrict__ R,
                     const float* __restrict__ bias,
                     float* __restrict__ out)
{
    const int cell = blockIdx.x;          // 0..191
    const int n = cell % NHEADS;
    const int b = cell / NHEADS;
    const int tid = threadIdx.x;          // 0..255
    const int g = tid >> 6;               // gate 0..3 (i,f,z,o)
    const int o = tid & 63;               // output element 0..63

    __shared__ __align__(16) float sh_h[2][HD];     // ping-pong hidden state
    __shared__ float sh_act[NG][HD];                // activated gates

    // ---- Load this thread's R row (R[n][g][o][0..63]) into registers, packed ----
    ull Rp[32];
    const float4* rrow = reinterpret_cast<const float4*>(
        R + (((size_t)n * NG + g) * HD + o) * HD);
#pragma unroll
    for (int k = 0; k < 16; ++k) {
        float4 v = rrow[k];
        Rp[2 * k]     = pk2(v.x, v.y);
        Rp[2 * k + 1] = pk2(v.z, v.w);
    }
    const float bv = bias[((size_t)n * NG + g) * HD + o];

    // ---- Initial states ----
    const size_t bn = (size_t)b * NHEADS + n;
    const size_t celloff = bn * HD + o;
    const float h0 = S0[bn * HD + o];
    float c = S0[(size_t)NCELLS * HD + bn * HD + o];   // replicated across the 4 g-threads

    float* out_h = out;                                 // [1025][192][64]
    float* out_c = out + (size_t)(T_STEPS + 1) * OROW;  // second state plane

    if (g == 0) {
        sh_h[0][o] = h0;
        out_h[celloff] = h0;        // t = 0 initial h
    } else if (g == 1) {
        out_c[celloff] = c;         // t = 0 initial c
    }

    // ---- Wx stream pointer for this thread ----
    const float* wx = Wx + bn * CELLSTR + (size_t)o * NG + g;

    __syncthreads();

    // Prefetch 4 timesteps of Wx
    float xc[4];
#pragma unroll
    for (int j = 0; j < 4; ++j)
        xc[j] = __ldcs(wx + (size_t)j * TSTRIDE);

    int p = 0;
    float* oh = out_h + OROW + celloff;   // points at t=1 row
    float* oc = out_c + OROW + celloff;

    for (int t0 = 0; t0 < T_STEPS; t0 += 4) {
        // Prefetch next 4 steps while computing current 4 (covers DRAM latency)
        float xn[4];
        const bool more = (t0 + 4) < T_STEPS;
#pragma unroll
        for (int j = 0; j < 4; ++j)
            xn[j] = more ? __ldcs(wx + (size_t)(t0 + 4 + j) * TSTRIDE) : 0.0f;

#pragma unroll
        for (int j = 0; j < 4; ++j) {
            // ---- gate pre-activation: x + b + R[n,g,o,:] . h ----
            ull acc0 = pk2(xc[j] + bv, 0.0f);
            ull acc1 = 0ULL, acc2 = 0ULL, acc3 = 0ULL;
            const ulonglong2* hb = reinterpret_cast<const ulonglong2*>(sh_h[p]);
#pragma unroll
            for (int k = 0; k < 16; k += 2) {
                ulonglong2 hv0 = hb[k];       // LDS.128 broadcast
                ulonglong2 hv1 = hb[k + 1];
                ffma2(acc0, Rp[2 * k],     hv0.x);
                ffma2(acc1, Rp[2 * k + 1], hv0.y);
                ffma2(acc2, Rp[2 * k + 2], hv1.x);
                ffma2(acc3, Rp[2 * k + 3], hv1.y);
            }
            float lo, hi, sum;
            upk2(acc0, lo, hi); sum  = lo + hi;
            upk2(acc1, lo, hi); sum += lo + hi;
            upk2(acc2, lo, hi); sum += lo + hi;
            upk2(acc3, lo, hi); sum += lo + hi;

            // warp-uniform branch (64 threads per gate = 2 warps)
            const float a = (g == 2) ? ftanh_f(sum) : fsigmoid(sum);
            sh_act[g][o] = a;
            __syncthreads();

            // ---- cell update (redundant across the 4 g-threads; deterministic) ----
            const float gi = sh_act[0][o];
            const float gf = sh_act[1][o];
            const float gz = sh_act[2][o];
            const float go = sh_act[3][o];
            c = gf * c + gi * gz;
            const float h = go * ftanh_f(c);

            if (g == 0) {
                sh_h[p ^ 1][o] = h;   // write other buffer: no race with readers of sh_h[p]
                *oh = h;
            } else if (g == 1) {
                *oc = c;
            }
            __syncthreads();

            p ^= 1;
            oh += OROW;
            oc += OROW;
        }
#pragma unroll
        for (int j = 0; j < 4; ++j) xc[j] = xn[j];
    }
}

extern "C" void kernel_launch(void* const* d_in, const int* in_sizes, int n_in,
                              void* d_out, int out_size)
{
    const float* Wx   = (const float*)d_in[0];  // [1024,16,12,64,4]
    const float* S0   = (const float*)d_in[1];  // [2,16,12,64]
    const float* R    = (const float*)d_in[2];  // [12,4,64,64]
    const float* bias = (const float*)d_in[3];  // [12,4,64]
    float* out = (float*)d_out;                 // [2,1025,16,12,64]

    flashrnn_lstm_kernel<<<NCELLS, 256>>>(Wx, S0, R, bias, out);
}